// round 14
// baseline (speedup 1.0000x reference)
#include <cuda_runtime.h>
#include <cuda_bf16.h>
#include <cstdint>

// CholeskyMMNet: mma.sync bf16 hi/lo split; B fragments pre-shuffled in gmem
// (direct LDG); A smem-resident.
// R13: 16 rows/CTA, 8 warps (warp tile m16xn64), 85-reg cap -> 3 CTAs/SM
// (24 warps, was 16). M = L@L^T via MMA (2 passes, staging zeroed once).

#define QDIM 32
#define HDIM 512
#define NTRIL 528
#define BIAS_F 2.0f

// fragment-layout weights: uint4 index ((S*16 + J)*4 + g)*32 + lane
//   g0 = hi, n8 blocks {0,1}; g1 = hi {2,3}; g2 = lo {0,1}; g3 = lo {2,3}
__device__ uint4 g_Fi[2  * 16 * 4 * 32];
__device__ uint4 g_F1[32 * 16 * 4 * 32];
__device__ uint4 g_F2[32 * 16 * 4 * 32];
__device__ uint4 g_Fu[32 * 16 * 4 * 32];
__device__ uint4 g_Fo[32 * 16 * 4 * 32];   // W_o cols 0..511
__device__ uint4 g_Ft[32 * 4 * 32];        // W_o cols 512..527 (padded), (S*4+g)*32+lane

// xs: [16 rows][2048B] = hi 1KB | lo 1KB per row, XOR-swizzled (0..32K)
// Lp overlay: [16][528] fp32 at byte 0 (= 33792 B, after final epilogue)
// PART (layer-5 tail partials, 8 warps x [16][16] f32 = 8192 B) at 33792
// M staging (dense L bf16, 8 rows, hi|lo, 80B stride) also at 33792 (later)
#define XS(r,k,sel) ((r)*2048 + ((((sel)<<10) + ((k)<<1)) ^ (((r)&7)<<4)))
#define PART_OFF 33792
#define LD_BASE  33792
#define LD_SELSZ 20480            // 8 rows * 32 * 80 B
#define SMEM_BYTES (LD_BASE + 2 * LD_SELSZ)   // 74752

__device__ __forceinline__ uint32_t smem_u32(const void* p) {
    uint32_t a;
    asm("{ .reg .u64 t; cvta.to.shared.u64 t, %1; cvt.u32.u64 %0, t; }" : "=r"(a) : "l"(p));
    return a;
}

#define LDSM4(d, addr) \
    asm volatile("ldmatrix.sync.aligned.m8n8.x4.shared.b16 {%0,%1,%2,%3}, [%4];" \
        : "=r"((d)[0]),"=r"((d)[1]),"=r"((d)[2]),"=r"((d)[3]) : "r"(addr))

#define MMA16816(c, a, b0, b1) \
    asm volatile("mma.sync.aligned.m16n8k16.row.col.f32.bf16.bf16.f32 " \
        "{%0,%1,%2,%3}, {%4,%5,%6,%7}, {%8,%9}, {%0,%1,%2,%3};" \
        : "+f"((c)[0]),"+f"((c)[1]),"+f"((c)[2]),"+f"((c)[3]) \
        : "r"((a)[0]),"r"((a)[1]),"r"((a)[2]),"r"((a)[3]), "r"(b0),"r"(b1))

__device__ __forceinline__ void split2(float a, float b, uint32_t& h, uint32_t& l) {
    __nv_bfloat16 ha = __float2bfloat16(a), hb = __float2bfloat16(b);
    __nv_bfloat162 hp = __halves2bfloat162(ha, hb);
    __nv_bfloat162 lp = __halves2bfloat162(
        __float2bfloat16(a - __bfloat162float(ha)),
        __float2bfloat16(b - __bfloat162float(hb)));
    h = *(uint32_t*)&hp; l = *(uint32_t*)&lp;
}
__device__ __forceinline__ float rd2(const char* sm, int off0, int off1, int idx) {
    __nv_bfloat162 h = *(const __nv_bfloat162*)(sm + off0);
    __nv_bfloat162 l = *(const __nv_bfloat162*)(sm + off1);
    return idx ? (__bfloat162float(h.y) + __bfloat162float(l.y))
               : (__bfloat162float(h.x) + __bfloat162float(l.x));
}

__device__ __forceinline__ void ldB4(uint4* b, const uint4* __restrict__ gF,
                                     int S, int J, int lane) {
    const uint4* p = gF + ((size_t)(S * 16 + J) * 4) * 32 + lane;
    b[0] = __ldg(p);       b[1] = __ldg(p + 32);
    b[2] = __ldg(p + 64);  b[3] = __ldg(p + 96);
}

// 12 MMAs: hh (q0,q1), hl (q2,q3), lh (q0,q1) into one m16n32 acc block
__device__ __forceinline__ void mma12(float* A, const uint32_t ah[4], const uint32_t al[4],
                                      const uint4& q0, const uint4& q1,
                                      const uint4& q2, const uint4& q3) {
    MMA16816(A+0,  ah, q0.x, q0.y); MMA16816(A+4,  ah, q0.z, q0.w);
    MMA16816(A+8,  ah, q1.x, q1.y); MMA16816(A+12, ah, q1.z, q1.w);
    MMA16816(A+0,  ah, q2.x, q2.y); MMA16816(A+4,  ah, q2.z, q2.w);
    MMA16816(A+8,  ah, q3.x, q3.y); MMA16816(A+12, ah, q3.z, q3.w);
    MMA16816(A+0,  al, q0.x, q0.y); MMA16816(A+4,  al, q0.z, q0.w);
    MMA16816(A+8,  al, q1.x, q1.y); MMA16816(A+12, al, q1.z, q1.w);
}

// D[16][512] = X @ W^T; warp tile m16 x n64 (J blocks 2w, 2w+1)
template<int NS, bool RELU, bool RES, bool TO_LP>
__device__ void tc_layer(char* __restrict__ sm, uint32_t smb,
                         const uint4* __restrict__ gF,
                         const float* __restrict__ bias)
{
    const int tid = threadIdx.x, warp = tid >> 5, lane = tid & 31;
    float acc[32];
    #pragma unroll
    for (int i = 0; i < 32; i++) acc[i] = 0.f;

    uint4 bq[8];
    ldB4(bq,     gF, 0, 2 * warp,     lane);
    ldB4(bq + 4, gF, 0, 2 * warp + 1, lane);

    const int k8 = (lane >> 4) << 3;
    const int rb = lane & 15;

    #pragma unroll 1
    for (int S = 0; S < NS; S++) {
        const int kk = S * 16 + k8;
        uint32_t ah[4], al[4];
        LDSM4(ah, smb + XS(rb, kk, 0));
        LDSM4(al, smb + XS(rb, kk, 1));
        mma12(acc +  0, ah, al, bq[0], bq[1], bq[2], bq[3]);
        if (S + 1 < NS) ldB4(bq, gF, S + 1, 2 * warp, lane);
        mma12(acc + 16, ah, al, bq[4], bq[5], bq[6], bq[7]);
        if (S + 1 < NS) ldB4(bq + 4, gF, S + 1, 2 * warp + 1, lane);
    }
    __syncthreads();   // all mainloop ldsm reads of xs complete

    float tv = 0.f;
    int tr = 0, tcc = 0;
    if (TO_LP) {
        // ---- mini-GEMM: Lp cols 512..527, split-K (warp w -> k chunk 64w..64w+63)
        float at[8];
        #pragma unroll
        for (int i = 0; i < 8; i++) at[i] = 0.f;
        #pragma unroll
        for (int s4 = 0; s4 < 4; s4++) {
            const int S = warp * 4 + s4;
            const int kk = S * 16 + k8;
            uint4 th = __ldg(g_Ft + (S * 4 + 0) * 32 + lane);   // hi j0,j1
            uint4 tl = __ldg(g_Ft + (S * 4 + 2) * 32 + lane);   // lo j0,j1
            uint32_t bh[4], bl[4];
            LDSM4(bh, smb + XS(rb, kk, 0));
            LDSM4(bl, smb + XS(rb, kk, 1));
            MMA16816(at+0, bh, th.x, th.y); MMA16816(at+4, bh, th.z, th.w);
            MMA16816(at+0, bh, tl.x, tl.y); MMA16816(at+4, bh, tl.z, tl.w);
            MMA16816(at+0, bl, th.x, th.y); MMA16816(at+4, bl, th.z, th.w);
        }
        float* part = (float*)(sm + PART_OFF) + warp * 256;   // [16][16]
        #pragma unroll
        for (int j = 0; j < 2; j++) {
            const int r0 = lane >> 2, r1 = r0 + 8;
            const int c  = j * 8 + 2 * (lane & 3);
            const float* a = at + j * 4;
            part[r0 * 16 + c] = a[0]; part[r0 * 16 + c + 1] = a[1];
            part[r1 * 16 + c] = a[2]; part[r1 * 16 + c + 1] = a[3];
        }
        __syncthreads();   // partials visible; all xs reads complete

        tr = tid >> 4; tcc = tid & 15;                         // 16x16 = 256 values
        const float* pb = (const float*)(sm + PART_OFF);
        #pragma unroll
        for (int w = 0; w < 8; w++)
            tv += pb[w * 256 + tr * 16 + tcc];
        tv += __ldg(bias + 512 + tcc);
    }

    #pragma unroll
    for (int Jl = 0; Jl < 2; Jl++)
        #pragma unroll
        for (int j = 0; j < 4; j++) {
            const int c  = warp * 64 + Jl * 32 + j * 8 + 2 * (lane & 3);
            const int r0 = lane >> 2, r1 = r0 + 8;
            const float* a = acc + Jl * 16 + j * 4;
            float b0v = __ldg(bias + c), b1v = __ldg(bias + c + 1);
            float y00 = a[0] + b0v, y01 = a[1] + b1v;
            float y10 = a[2] + b0v, y11 = a[3] + b1v;
            if (RELU) {
                y00 = fmaxf(y00, 0.f); y01 = fmaxf(y01, 0.f);
                y10 = fmaxf(y10, 0.f); y11 = fmaxf(y11, 0.f);
            }
            if (RES) {
                y00 += rd2(sm, XS(r0, c, 0), XS(r0, c, 1), 0);
                y01 += rd2(sm, XS(r0, c, 0), XS(r0, c, 1), 1);
                y10 += rd2(sm, XS(r1, c, 0), XS(r1, c, 1), 0);
                y11 += rd2(sm, XS(r1, c, 0), XS(r1, c, 1), 1);
            }
            if (TO_LP) {
                float* lp = (float*)sm;
                lp[r0 * NTRIL + c] = y00; lp[r0 * NTRIL + c + 1] = y01;
                lp[r1 * NTRIL + c] = y10; lp[r1 * NTRIL + c + 1] = y11;
            } else {
                uint32_t h, l;
                split2(y00, y01, h, l);
                *(uint32_t*)(sm + XS(r0, c, 0)) = h;
                *(uint32_t*)(sm + XS(r0, c, 1)) = l;
                split2(y10, y11, h, l);
                *(uint32_t*)(sm + XS(r1, c, 0)) = h;
                *(uint32_t*)(sm + XS(r1, c, 1)) = l;
            }
        }
    if (TO_LP) {
        float* lp = (float*)sm;
        lp[tr * NTRIL + 512 + tcc] = tv;
    }
    __syncthreads();
}

__global__ void __launch_bounds__(256, 3)
main_kernel(const float* __restrict__ q,
            const float* __restrict__ bin, const float* __restrict__ bh1,
            const float* __restrict__ bh2, const float* __restrict__ bout,
            const float* __restrict__ bo,  float* __restrict__ out)
{
    extern __shared__ char sm[];
    const uint32_t smb = smem_u32(sm);
    const int tid = threadIdx.x, warp = tid >> 5, lane = tid & 31;
    const int row0 = blockIdx.x * 16;

    {   // stage q (16x32 fp32) into xs hi/lo: thread -> (r, 2 cols)
        int r = tid >> 4, kq = (tid & 15) * 2;
        float2 v = *(const float2*)(q + (size_t)(row0 + r) * QDIM + kq);
        uint32_t h, l;
        split2(v.x, v.y, h, l);
        *(uint32_t*)(sm + XS(r, kq, 0)) = h;
        *(uint32_t*)(sm + XS(r, kq, 1)) = l;
    }
    __syncthreads();

    tc_layer<2,  true,  false, false>(sm, smb, g_Fi, bin);
    tc_layer<32, true,  true,  false>(sm, smb, g_F1, bh1);
    tc_layer<32, true,  true,  false>(sm, smb, g_F2, bh2);
    tc_layer<32, false, false, false>(sm, smb, g_Fu, bout);
    tc_layer<32, false, false, true >(sm, smb, g_Fo, bo);

    // ---- M = L @ L^T via MMA, 2 passes x 8 rows ----
    // zero staging ONCE: upper triangle stays zero; fill overwrites lower+diag
    {
        uint4 z = make_uint4(0, 0, 0, 0);
        uint4* zp = (uint4*)(sm + LD_BASE);
        #pragma unroll
        for (int i = 0; i < (2 * LD_SELSZ) / (16 * 256); i++)
            zp[tid + i * 256] = z;
    }
    __syncthreads();

    const float* lpo = (const float*)sm;   // Lp overlay [16][528]
    for (int pass = 0; pass < 2; pass++) {
        // fill dense L (bf16 hi/lo) for r = pass*8 .. pass*8+7
        for (int e = tid; e < 8 * NTRIL; e += 256) {
            int rr = e / NTRIL, t = e - rr * NTRIL;
            int i, k; float v;
            if (t < 32) {
                i = t; k = t;
                v = lpo[(pass * 8 + rr) * NTRIL + t] + BIAS_F;
            } else {
                int p2 = t - 32;
                i = (int)((1.0f + sqrtf((float)(1 + 8 * p2))) * 0.5f);
                int base = (i * (i - 1)) >> 1;
                if (p2 < base)          { i--; base = (i * (i - 1)) >> 1; }
                else if (p2 >= base + i){ i++; base = (i * (i - 1)) >> 1; }
                k = p2 - base;
                v = lpo[(pass * 8 + rr) * NTRIL + t];
            }
            __nv_bfloat16 h = __float2bfloat16(v);
            __nv_bfloat16 l = __float2bfloat16(v - __bfloat162float(h));
            int boff = LD_BASE + rr * 2560 + i * 80 + ((k >> 3) << 4) + ((k & 7) << 1);
            *(__nv_bfloat16*)(sm + boff) = h;
            *(__nv_bfloat16*)(sm + boff + LD_SELSZ) = l;
        }
        __syncthreads();

        // warp w computes M for r = pass*8 + w  (32x32x32 syrk via MMA)
        {
            float am[32];
            #pragma unroll
            for (int i = 0; i < 32; i++) am[i] = 0.f;
            const int rw = lane & 15, half = lane >> 4;
            #pragma unroll
            for (int s = 0; s < 2; s++) {
                uint32_t f0h[4], f0l[4], f1h[4], f1l[4];
                uint32_t a0 = smb + LD_BASE + warp * 2560 + rw * 80 + (2 * s + half) * 16;
                uint32_t a1 = a0 + 16 * 80;
                LDSM4(f0h, a0); LDSM4(f0l, a0 + LD_SELSZ);
                LDSM4(f1h, a1); LDSM4(f1l, a1 + LD_SELSZ);
                // hh
                MMA16816(am+0,  f0h, f0h[0], f0h[2]); MMA16816(am+4,  f0h, f0h[1], f0h[3]);
                MMA16816(am+8,  f0h, f1h[0], f1h[2]); MMA16816(am+12, f0h, f1h[1], f1h[3]);
                MMA16816(am+16, f1h, f0h[0], f0h[2]); MMA16816(am+20, f1h, f0h[1], f0h[3]);
                MMA16816(am+24, f1h, f1h[0], f1h[2]); MMA16816(am+28, f1h, f1h[1], f1h[3]);
                // hl (A hi, B lo)
                MMA16816(am+0,  f0h, f0l[0], f0l[2]); MMA16816(am+4,  f0h, f0l[1], f0l[3]);
                MMA16816(am+8,  f0h, f1l[0], f1l[2]); MMA16816(am+12, f0h, f1l[1], f1l[3]);
                MMA16816(am+16, f1h, f0l[0], f0l[2]); MMA16816(am+20, f1h, f0l[1], f0l[3]);
                MMA16816(am+24, f1h, f1l[0], f1l[2]); MMA16816(am+28, f1h, f1l[1], f1l[3]);
                // lh (A lo, B hi)
                MMA16816(am+0,  f0l, f0h[0], f0h[2]); MMA16816(am+4,  f0l, f0h[1], f0h[3]);
                MMA16816(am+8,  f0l, f1h[0], f1h[2]); MMA16816(am+12, f0l, f1h[1], f1h[3]);
                MMA16816(am+16, f1l, f0h[0], f0h[2]); MMA16816(am+20, f1l, f0h[1], f0h[3]);
                MMA16816(am+24, f1l, f1h[0], f1h[2]); MMA16816(am+28, f1l, f1h[1], f1h[3]);
            }
            float* orow = out + (size_t)(row0 + pass * 8 + warp) * 1024;
            #pragma unroll
            for (int ib = 0; ib < 2; ib++)
                #pragma unroll
                for (int jb = 0; jb < 4; jb++) {
                    const float* a = am + (ib * 4 + jb) * 4;
                    int r0 = ib * 16 + (lane >> 2), r1 = r0 + 8;
                    int col = jb * 8 + 2 * (lane & 3);
                    *(float2*)(orow + r0 * 32 + col) = make_float2(a[0], a[1]);
                    *(float2*)(orow + r1 * 32 + col) = make_float2(a[2], a[3]);
                }
        }
        __syncthreads();   // before next pass's fill overwrites staging
    }
}

// ---------------- prep: weights -> fragment layout (unchanged) ----------------
#define FI_U32   (2 * 16 * 4 * 32 * 4)
#define FL_U32   (32 * 16 * 4 * 32 * 4)
#define MAIN_U32 (FI_U32 + 4 * FL_U32)
#define FT_U32   (32 * 4 * 32 * 4)

__global__ void prep_kernel(const float* __restrict__ Win, const float* __restrict__ Wh1,
                            const float* __restrict__ Wh2, const float* __restrict__ Wou,
                            const float* __restrict__ Wo)
{
    const int total = MAIN_U32 + FT_U32;
    for (int e = blockIdx.x * blockDim.x + threadIdx.x; e < total;
         e += gridDim.x * blockDim.x) {
        if (e < MAIN_U32) {
            const float* W; uint32_t* dst; int t, ncols;
            if (e < FI_U32) { W = Win; dst = (uint32_t*)g_Fi; t = e; ncols = 512; }
            else {
                int le = e - FI_U32, ly = le / FL_U32;
                t = le - ly * FL_U32;
                ncols = (ly == 3) ? 528 : 512;
                W   = (ly == 0) ? Wh1 : (ly == 1) ? Wh2 : (ly == 2) ? Wou : Wo;
                dst = (uint32_t*)((ly == 0) ? g_F1 : (ly == 1) ? g_F2 :
                                  (ly == 2) ? g_Fu : g_Fo);
            }
            int c = t & 3, l = (t >> 2) & 31, g = (t >> 7) & 3;
            int J = (t >> 9) & 15, S = t >> 13;
            int jl  = (g & 1) * 2 + (c >> 1);
            int sel = g >> 1;
            int n   = J * 32 + jl * 8 + (l >> 2);
            int k0  = S * 16 + (c & 1) * 8 + 2 * (l & 3);
            float v0 = __ldg(W + (size_t)k0 * ncols + n);
            float v1 = __ldg(W + (size_t)(k0 + 1) * ncols + n);
            __nv_bfloat16 h0 = __float2bfloat16(v0), h1 = __float2bfloat16(v1);
            __nv_bfloat16 o0, o1;
            if (sel == 0) { o0 = h0; o1 = h1; }
            else {
                o0 = __float2bfloat16(v0 - __bfloat162float(h0));
                o1 = __float2bfloat16(v1 - __bfloat162float(h1));
            }
            __nv_bfloat162 p = __halves2bfloat162(o0, o1);
            dst[t] = *(uint32_t*)&p;
        } else {
            int t = e - MAIN_U32;
            int c = t & 3, l = (t >> 2) & 31, g = (t >> 7) & 3;
            int S = t >> 9;
            int jl  = (g & 1) * 2 + (c >> 1);
            int sel = g >> 1;
            int n   = 512 + jl * 8 + (l >> 2);
            int k0  = S * 16 + (c & 1) * 8 + 2 * (l & 3);
            float v0 = (n < NTRIL) ? __ldg(Wo + (size_t)k0 * NTRIL + n) : 0.f;
            float v1 = (n < NTRIL) ? __ldg(Wo + (size_t)(k0 + 1) * NTRIL + n) : 0.f;
            __nv_bfloat16 h0 = __float2bfloat16(v0), h1 = __float2bfloat16(v1);
            __nv_bfloat16 o0, o1;
            if (sel == 0) { o0 = h0; o1 = h1; }
            else {
                o0 = __float2bfloat16(v0 - __bfloat162float(h0));
                o1 = __float2bfloat16(v1 - __bfloat162float(h1));
            }
            __nv_bfloat162 p = __halves2bfloat162(o0, o1);
            ((uint32_t*)g_Ft)[t] = *(uint32_t*)&p;
        }
    }
}

extern "C" void kernel_launch(void* const* d_in, const int* in_sizes, int n_in,
                              void* d_out, int out_size)
{
    const float* q    = (const float*)d_in[0];
    const float* Win  = (const float*)d_in[1];
    const float* bin  = (const float*)d_in[2];
    const float* Wh1  = (const float*)d_in[3];
    const float* bh1  = (const float*)d_in[4];
    const float* Wh2  = (const float*)d_in[5];
    const float* bh2  = (const float*)d_in[6];
    const float* Wout = (const float*)d_in[7];
    const float* bout = (const float*)d_in[8];
    const float* Wo   = (const float*)d_in[9];
    const float* bo   = (const float*)d_in[10];
    float* out = (float*)d_out;

    const int B = in_sizes[0] / QDIM;   // 65536

    cudaFuncSetAttribute(main_kernel,
                         cudaFuncAttributeMaxDynamicSharedMemorySize, SMEM_BYTES);

    prep_kernel<<<148, 512>>>(Win, Wh1, Wh2, Wout, Wo);
    main_kernel<<<B / 16, 256, SMEM_BYTES>>>(q, bin, bh1, bh2, bout, bo, out);
}

// round 15
// speedup vs baseline: 1.0386x; 1.0386x over previous
#include <cuda_runtime.h>
#include <cuda_bf16.h>
#include <cstdint>

// CholeskyMMNet: mma.sync bf16 hi/lo split; B fragments pre-shuffled in gmem
// (direct LDG); A smem-resident; 32 rows/CTA, 256 thr, 2 CTAs/SM (R12 config —
// best measured). R15: non-volatile MMA asm (lets ptxas pipeline), M staging
// zeroed once.

#define QDIM 32
#define HDIM 512
#define NTRIL 528
#define BIAS_F 2.0f

// fragment-layout weights: uint4 index ((S*16 + J)*4 + g)*32 + lane
//   g0 = hi, n8 blocks {0,1}; g1 = hi {2,3}; g2 = lo {0,1}; g3 = lo {2,3}
__device__ uint4 g_Fi[2  * 16 * 4 * 32];
__device__ uint4 g_F1[32 * 16 * 4 * 32];
__device__ uint4 g_F2[32 * 16 * 4 * 32];
__device__ uint4 g_Fu[32 * 16 * 4 * 32];
__device__ uint4 g_Fo[32 * 16 * 4 * 32];   // W_o cols 0..511
__device__ uint4 g_Ft[32 * 4 * 32];        // W_o cols 512..527 (padded), (S*4+g)*32+lane

// xs: [32 rows][2048B] = hi 1KB | lo 1KB per row, XOR-swizzled (0..64K)
// Lp overlay: [32][528] fp32 at byte 0 (= 67584 B, after final epilogue)
// tail partials: [8 warps][32][16] fp32 at PART_OFF (layer 5 only)
// M staging: dense L bf16, 8 rows, hi|lo, 80B row stride, at LD_BASE
#define XS(r,k,sel) ((r)*2048 + ((((sel)<<10) + ((k)<<1)) ^ (((r)&7)<<4)))
#define PART_OFF 67584
#define LD_BASE  67584
#define LD_SELSZ 20480            // 8 r * 32 rows * 80 B
#define SMEM_BYTES (LD_BASE + 2 * LD_SELSZ)   // 108544

__device__ __forceinline__ uint32_t smem_u32(const void* p) {
    uint32_t a;
    asm("{ .reg .u64 t; cvta.to.shared.u64 t, %1; cvt.u32.u64 %0, t; }" : "=r"(a) : "l"(p));
    return a;
}

#define LDSM4(d, addr) \
    asm volatile("ldmatrix.sync.aligned.m8n8.x4.shared.b16 {%0,%1,%2,%3}, [%4];" \
        : "=r"((d)[0]),"=r"((d)[1]),"=r"((d)[2]),"=r"((d)[3]) : "r"(addr))

// NOTE: non-volatile — pure register dataflow; ptxas may schedule freely.
#define MMA16816(c, a, b0, b1) \
    asm("mma.sync.aligned.m16n8k16.row.col.f32.bf16.bf16.f32 " \
        "{%0,%1,%2,%3}, {%4,%5,%6,%7}, {%8,%9}, {%0,%1,%2,%3};" \
        : "+f"((c)[0]),"+f"((c)[1]),"+f"((c)[2]),"+f"((c)[3]) \
        : "r"((a)[0]),"r"((a)[1]),"r"((a)[2]),"r"((a)[3]), "r"(b0),"r"(b1))

__device__ __forceinline__ void split2(float a, float b, uint32_t& h, uint32_t& l) {
    __nv_bfloat16 ha = __float2bfloat16(a), hb = __float2bfloat16(b);
    __nv_bfloat162 hp = __halves2bfloat162(ha, hb);
    __nv_bfloat162 lp = __halves2bfloat162(
        __float2bfloat16(a - __bfloat162float(ha)),
        __float2bfloat16(b - __bfloat162float(hb)));
    h = *(uint32_t*)&hp; l = *(uint32_t*)&lp;
}
__device__ __forceinline__ float rd2(const char* sm, int off0, int off1, int idx) {
    __nv_bfloat162 h = *(const __nv_bfloat162*)(sm + off0);
    __nv_bfloat162 l = *(const __nv_bfloat162*)(sm + off1);
    return idx ? (__bfloat162float(h.y) + __bfloat162float(l.y))
               : (__bfloat162float(h.x) + __bfloat162float(l.x));
}

__device__ __forceinline__ void ldB4(uint4* b, const uint4* __restrict__ gF,
                                     int S, int J, int lane) {
    const uint4* p = gF + ((size_t)(S * 16 + J) * 4) * 32 + lane;
    b[0] = __ldg(p);       b[1] = __ldg(p + 32);
    b[2] = __ldg(p + 64);  b[3] = __ldg(p + 96);
}

// 12 MMAs: hh (q0,q1), hl (q2,q3), lh (q0,q1)
__device__ __forceinline__ void mma12(float* A, const uint32_t ah[4], const uint32_t al[4],
                                      const uint4& q0, const uint4& q1,
                                      const uint4& q2, const uint4& q3) {
    MMA16816(A+0,  ah, q0.x, q0.y); MMA16816(A+4,  ah, q0.z, q0.w);
    MMA16816(A+8,  ah, q1.x, q1.y); MMA16816(A+12, ah, q1.z, q1.w);
    MMA16816(A+0,  ah, q2.x, q2.y); MMA16816(A+4,  ah, q2.z, q2.w);
    MMA16816(A+8,  ah, q3.x, q3.y); MMA16816(A+12, ah, q3.z, q3.w);
    MMA16816(A+0,  al, q0.x, q0.y); MMA16816(A+4,  al, q0.z, q0.w);
    MMA16816(A+8,  al, q1.x, q1.y); MMA16816(A+12, al, q1.z, q1.w);
}

// D[32][512] = X @ W^T; warp tile m32 x n64 (J blocks 2w, 2w+1)
template<int NS, bool RELU, bool RES, bool TO_LP>
__device__ void tc_layer(char* __restrict__ sm, uint32_t smb,
                         const uint4* __restrict__ gF,
                         const float* __restrict__ bias)
{
    const int tid = threadIdx.x, warp = tid >> 5, lane = tid & 31;
    float acc[64];
    #pragma unroll
    for (int i = 0; i < 64; i++) acc[i] = 0.f;

    uint4 bq[8];
    ldB4(bq,     gF, 0, 2 * warp,     lane);
    ldB4(bq + 4, gF, 0, 2 * warp + 1, lane);

    #pragma unroll 1
    for (int S = 0; S < NS; S++) {
        const int kk = S * 16 + ((lane >> 4) << 3);
        const int rb = lane & 15;
        uint32_t ah0[4], al0[4], ah1[4], al1[4];
        LDSM4(ah0, smb + XS(rb, kk, 0));
        LDSM4(al0, smb + XS(rb, kk, 1));
        mma12(acc +  0, ah0, al0, bq[0], bq[1], bq[2], bq[3]);
        LDSM4(ah1, smb + XS(16 + rb, kk, 0));
        LDSM4(al1, smb + XS(16 + rb, kk, 1));
        mma12(acc + 32, ah1, al1, bq[0], bq[1], bq[2], bq[3]);
        if (S + 1 < NS) ldB4(bq, gF, S + 1, 2 * warp, lane);
        mma12(acc + 16, ah0, al0, bq[4], bq[5], bq[6], bq[7]);
        mma12(acc + 48, ah1, al1, bq[4], bq[5], bq[6], bq[7]);
        if (S + 1 < NS) ldB4(bq + 4, gF, S + 1, 2 * warp + 1, lane);
    }
    __syncthreads();   // all mainloop ldsm reads of xs complete

    float tv0 = 0.f, tv1 = 0.f;
    int tr = 0, tcc = 0;
    if (TO_LP) {
        // ---- mini-GEMM: Lp cols 512..527, split-K (warp w -> k chunk 64w..64w+63)
        float at[16];
        #pragma unroll
        for (int i = 0; i < 16; i++) at[i] = 0.f;
        #pragma unroll
        for (int s4 = 0; s4 < 4; s4++) {
            const int S = warp * 4 + s4;
            const int kk = S * 16 + ((lane >> 4) << 3);
            const int rb = lane & 15;
            uint4 th = __ldg(g_Ft + (S * 4 + 0) * 32 + lane);   // hi j0,j1
            uint4 tl = __ldg(g_Ft + (S * 4 + 2) * 32 + lane);   // lo j0,j1
            uint32_t bh0[4], bl0[4], bh1[4], bl1[4];
            LDSM4(bh0, smb + XS(rb, kk, 0));
            LDSM4(bl0, smb + XS(rb, kk, 1));
            LDSM4(bh1, smb + XS(16 + rb, kk, 0));
            LDSM4(bl1, smb + XS(16 + rb, kk, 1));
            MMA16816(at+0,  bh0, th.x, th.y); MMA16816(at+4,  bh0, th.z, th.w);
            MMA16816(at+0,  bh0, tl.x, tl.y); MMA16816(at+4,  bh0, tl.z, tl.w);
            MMA16816(at+0,  bl0, th.x, th.y); MMA16816(at+4,  bl0, th.z, th.w);
            MMA16816(at+8,  bh1, th.x, th.y); MMA16816(at+12, bh1, th.z, th.w);
            MMA16816(at+8,  bh1, tl.x, tl.y); MMA16816(at+12, bh1, tl.z, tl.w);
            MMA16816(at+8,  bl1, th.x, th.y); MMA16816(at+12, bl1, th.z, th.w);
        }
        float* part = (float*)(sm + PART_OFF) + warp * 32 * 16;
        #pragma unroll
        for (int mb = 0; mb < 2; mb++)
            #pragma unroll
            for (int j = 0; j < 2; j++) {
                const int r0 = mb * 16 + (lane >> 2), r1 = r0 + 8;
                const int c  = j * 8 + 2 * (lane & 3);
                const float* a = at + mb * 8 + j * 4;
                part[r0 * 16 + c] = a[0]; part[r0 * 16 + c + 1] = a[1];
                part[r1 * 16 + c] = a[2]; part[r1 * 16 + c + 1] = a[3];
            }
        __syncthreads();   // partials visible; all xs reads complete

        tr = tid >> 3; tcc = (tid & 7) * 2;
        const float* pb = (const float*)(sm + PART_OFF);
        #pragma unroll
        for (int w = 0; w < 8; w++) {
            tv0 += pb[w * 512 + tr * 16 + tcc];
            tv1 += pb[w * 512 + tr * 16 + tcc + 1];
        }
        tv0 += __ldg(bias + 512 + tcc);
        tv1 += __ldg(bias + 513 + tcc);
    }

    #pragma unroll
    for (int mb = 0; mb < 2; mb++)
        #pragma unroll
        for (int Jl = 0; Jl < 2; Jl++)
            #pragma unroll
            for (int j = 0; j < 4; j++) {
                const int c  = warp * 64 + Jl * 32 + j * 8 + 2 * (lane & 3);
                const int r0 = mb * 16 + (lane >> 2), r1 = r0 + 8;
                const float* a = acc + mb * 32 + Jl * 16 + j * 4;
                float b0v = __ldg(bias + c), b1v = __ldg(bias + c + 1);
                float y00 = a[0] + b0v, y01 = a[1] + b1v;
                float y10 = a[2] + b0v, y11 = a[3] + b1v;
                if (RELU) {
                    y00 = fmaxf(y00, 0.f); y01 = fmaxf(y01, 0.f);
                    y10 = fmaxf(y10, 0.f); y11 = fmaxf(y11, 0.f);
                }
                if (RES) {
                    y00 += rd2(sm, XS(r0, c, 0), XS(r0, c, 1), 0);
                    y01 += rd2(sm, XS(r0, c, 0), XS(r0, c, 1), 1);
                    y10 += rd2(sm, XS(r1, c, 0), XS(r1, c, 1), 0);
                    y11 += rd2(sm, XS(r1, c, 0), XS(r1, c, 1), 1);
                }
                if (TO_LP) {
                    float* lp = (float*)sm;
                    lp[r0 * NTRIL + c] = y00; lp[r0 * NTRIL + c + 1] = y01;
                    lp[r1 * NTRIL + c] = y10; lp[r1 * NTRIL + c + 1] = y11;
                } else {
                    uint32_t h, l;
                    split2(y00, y01, h, l);
                    *(uint32_t*)(sm + XS(r0, c, 0)) = h;
                    *(uint32_t*)(sm + XS(r0, c, 1)) = l;
                    split2(y10, y11, h, l);
                    *(uint32_t*)(sm + XS(r1, c, 0)) = h;
                    *(uint32_t*)(sm + XS(r1, c, 1)) = l;
                }
            }
    if (TO_LP) {
        float* lp = (float*)sm;
        lp[tr * NTRIL + 512 + tcc]     = tv0;
        lp[tr * NTRIL + 512 + tcc + 1] = tv1;
    }
    __syncthreads();
}

__global__ void __launch_bounds__(256, 2)
main_kernel(const float* __restrict__ q,
            const float* __restrict__ bin, const float* __restrict__ bh1,
            const float* __restrict__ bh2, const float* __restrict__ bout,
            const float* __restrict__ bo,  float* __restrict__ out)
{
    extern __shared__ char sm[];
    const uint32_t smb = smem_u32(sm);
    const int tid = threadIdx.x, warp = tid >> 5, lane = tid & 31;
    const int row0 = blockIdx.x * 32;

    {   // stage q (32x32 fp32) into xs hi/lo
        int r = tid >> 3, kq = (tid & 7) * 4;
        float4 v = *(const float4*)(q + (size_t)(row0 + r) * QDIM + kq);
        uint32_t h, l;
        split2(v.x, v.y, h, l);
        *(uint32_t*)(sm + XS(r, kq, 0)) = h;
        *(uint32_t*)(sm + XS(r, kq, 1)) = l;
        split2(v.z, v.w, h, l);
        *(uint32_t*)(sm + XS(r, kq + 2, 0)) = h;
        *(uint32_t*)(sm + XS(r, kq + 2, 1)) = l;
    }
    __syncthreads();

    tc_layer<2,  true,  false, false>(sm, smb, g_Fi, bin);
    tc_layer<32, true,  true,  false>(sm, smb, g_F1, bh1);
    tc_layer<32, true,  true,  false>(sm, smb, g_F2, bh2);
    tc_layer<32, false, false, false>(sm, smb, g_Fu, bout);
    tc_layer<32, false, false, true >(sm, smb, g_Fo, bo);

    // ---- M = L @ L^T via MMA, 4 passes x 8 rows ----
    // zero staging ONCE: upper triangle never dirtied; fill overwrites lower+diag
    {
        uint4 z = make_uint4(0, 0, 0, 0);
        uint4* zp = (uint4*)(sm + LD_BASE);
        #pragma unroll
        for (int i = 0; i < (2 * LD_SELSZ) / (16 * 256); i++)
            zp[tid + i * 256] = z;
    }
    __syncthreads();

    const float* lpo = (const float*)sm;   // Lp overlay [32][528]
    for (int pass = 0; pass < 4; pass++) {
        // fill dense L (bf16 hi/lo) for r = pass*8 .. pass*8+7
        for (int e = tid; e < 8 * NTRIL; e += 256) {
            int rr = e / NTRIL, t = e - rr * NTRIL;
            int i, k; float v;
            if (t < 32) {
                i = t; k = t;
                v = lpo[(pass * 8 + rr) * NTRIL + t] + BIAS_F;
            } else {
                int p2 = t - 32;
                i = (int)((1.0f + sqrtf((float)(1 + 8 * p2))) * 0.5f);
                int base = (i * (i - 1)) >> 1;
                if (p2 < base)          { i--; base = (i * (i - 1)) >> 1; }
                else if (p2 >= base + i){ i++; base = (i * (i - 1)) >> 1; }
                k = p2 - base;
                v = lpo[(pass * 8 + rr) * NTRIL + t];
            }
            __nv_bfloat16 h = __float2bfloat16(v);
            __nv_bfloat16 l = __float2bfloat16(v - __bfloat162float(h));
            int boff = LD_BASE + rr * 2560 + i * 80 + ((k >> 3) << 4) + ((k & 7) << 1);
            *(__nv_bfloat16*)(sm + boff) = h;
            *(__nv_bfloat16*)(sm + boff + LD_SELSZ) = l;
        }
        __syncthreads();

        // warp w computes M for r = pass*8 + w  (32x32x32 syrk via MMA)
        {
            float am[32];
            #pragma unroll
            for (int i = 0; i < 32; i++) am[i] = 0.f;
            const int rw = lane & 15, half = lane >> 4;
            #pragma unroll
            for (int s = 0; s < 2; s++) {
                uint32_t f0h[4], f0l[4], f1h[4], f1l[4];
                uint32_t a0 = smb + LD_BASE + warp * 2560 + rw * 80 + (2 * s + half) * 16;
                uint32_t a1 = a0 + 16 * 80;
                LDSM4(f0h, a0); LDSM4(f0l, a0 + LD_SELSZ);
                LDSM4(f1h, a1); LDSM4(f1l, a1 + LD_SELSZ);
                // hh
                MMA16816(am+0,  f0h, f0h[0], f0h[2]); MMA16816(am+4,  f0h, f0h[1], f0h[3]);
                MMA16816(am+8,  f0h, f1h[0], f1h[2]); MMA16816(am+12, f0h, f1h[1], f1h[3]);
                MMA16816(am+16, f1h, f0h[0], f0h[2]); MMA16816(am+20, f1h, f0h[1], f0h[3]);
                MMA16816(am+24, f1h, f1h[0], f1h[2]); MMA16816(am+28, f1h, f1h[1], f1h[3]);
                // hl (A hi, B lo)
                MMA16816(am+0,  f0h, f0l[0], f0l[2]); MMA16816(am+4,  f0h, f0l[1], f0l[3]);
                MMA16816(am+8,  f0h, f1l[0], f1l[2]); MMA16816(am+12, f0h, f1l[1], f1l[3]);
                MMA16816(am+16, f1h, f0l[0], f0l[2]); MMA16816(am+20, f1h, f0l[1], f0l[3]);
                MMA16816(am+24, f1h, f1l[0], f1l[2]); MMA16816(am+28, f1h, f1l[1], f1l[3]);
                // lh (A lo, B hi)
                MMA16816(am+0,  f0l, f0h[0], f0h[2]); MMA16816(am+4,  f0l, f0h[1], f0h[3]);
                MMA16816(am+8,  f0l, f1h[0], f1h[2]); MMA16816(am+12, f0l, f1h[1], f1h[3]);
                MMA16816(am+16, f1l, f0h[0], f0h[2]); MMA16816(am+20, f1l, f0h[1], f0h[3]);
                MMA16816(am+24, f1l, f1h[0], f1h[2]); MMA16816(am+28, f1l, f1h[1], f1h[3]);
            }
            float* orow = out + (size_t)(row0 + pass * 8 + warp) * 1024;
            #pragma unroll
            for (int ib = 0; ib < 2; ib++)
                #pragma unroll
                for (int jb = 0; jb < 4; jb++) {
                    const float* a = am + (ib * 4 + jb) * 4;
                    int r0 = ib * 16 + (lane >> 2), r1 = r0 + 8;
                    int col = jb * 8 + 2 * (lane & 3);
                    *(float2*)(orow + r0 * 32 + col) = make_float2(a[0], a[1]);
                    *(float2*)(orow + r1 * 32 + col) = make_float2(a[2], a[3]);
                }
        }
        __syncthreads();   // before next pass's fill overwrites staging
    }
}

// ---------------- prep: weights -> fragment layout (unchanged) ----------------
#define FI_U32   (2 * 16 * 4 * 32 * 4)
#define FL_U32   (32 * 16 * 4 * 32 * 4)
#define MAIN_U32 (FI_U32 + 4 * FL_U32)
#define FT_U32   (32 * 4 * 32 * 4)

__global__ void prep_kernel(const float* __restrict__ Win, const float* __restrict__ Wh1,
                            const float* __restrict__ Wh2, const float* __restrict__ Wou,
                            const float* __restrict__ Wo)
{
    const int total = MAIN_U32 + FT_U32;
    for (int e = blockIdx.x * blockDim.x + threadIdx.x; e < total;
         e += gridDim.x * blockDim.x) {
        if (e < MAIN_U32) {
            const float* W; uint32_t* dst; int t, ncols;
            if (e < FI_U32) { W = Win; dst = (uint32_t*)g_Fi; t = e; ncols = 512; }
            else {
                int le = e - FI_U32, ly = le / FL_U32;
                t = le - ly * FL_U32;
                ncols = (ly == 3) ? 528 : 512;
                W   = (ly == 0) ? Wh1 : (ly == 1) ? Wh2 : (ly == 2) ? Wou : Wo;
                dst = (uint32_t*)((ly == 0) ? g_F1 : (ly == 1) ? g_F2 :
                                  (ly == 2) ? g_Fu : g_Fo);
            }
            int c = t & 3, l = (t >> 2) & 31, g = (t >> 7) & 3;
            int J = (t >> 9) & 15, S = t >> 13;
            int jl  = (g & 1) * 2 + (c >> 1);
            int sel = g >> 1;
            int n   = J * 32 + jl * 8 + (l >> 2);
            int k0  = S * 16 + (c & 1) * 8 + 2 * (l & 3);
            float v0 = __ldg(W + (size_t)k0 * ncols + n);
            float v1 = __ldg(W + (size_t)(k0 + 1) * ncols + n);
            __nv_bfloat16 h0 = __float2bfloat16(v0), h1 = __float2bfloat16(v1);
            __nv_bfloat16 o0, o1;
            if (sel == 0) { o0 = h0; o1 = h1; }
            else {
                o0 = __float2bfloat16(v0 - __bfloat162float(h0));
                o1 = __float2bfloat16(v1 - __bfloat162float(h1));
            }
            __nv_bfloat162 p = __halves2bfloat162(o0, o1);
            dst[t] = *(uint32_t*)&p;
        } else {
            int t = e - MAIN_U32;
            int c = t & 3, l = (t >> 2) & 31, g = (t >> 7) & 3;
            int S = t >> 9;
            int jl  = (g & 1) * 2 + (c >> 1);
            int sel = g >> 1;
            int n   = 512 + jl * 8 + (l >> 2);
            int k0  = S * 16 + (c & 1) * 8 + 2 * (l & 3);
            float v0 = (n < NTRIL) ? __ldg(Wo + (size_t)k0 * NTRIL + n) : 0.f;
            float v1 = (n < NTRIL) ? __ldg(Wo + (size_t)(k0 + 1) * NTRIL + n) : 0.f;
            __nv_bfloat16 h0 = __float2bfloat16(v0), h1 = __float2bfloat16(v1);
            __nv_bfloat16 o0, o1;
            if (sel == 0) { o0 = h0; o1 = h1; }
            else {
                o0 = __float2bfloat16(v0 - __bfloat162float(h0));
                o1 = __float2bfloat16(v1 - __bfloat162float(h1));
            }
            __nv_bfloat162 p = __halves2bfloat162(o0, o1);
            ((uint32_t*)g_Ft)[t] = *(uint32_t*)&p;
        }
    }
}

extern "C" void kernel_launch(void* const* d_in, const int* in_sizes, int n_in,
                              void* d_out, int out_size)
{
    const float* q    = (const float*)d_in[0];
    const float* Win  = (const float*)d_in[1];
    const float* bin  = (const float*)d_in[2];
    const float* Wh1  = (const float*)d_in[3];
    const float* bh1  = (const float*)d_in[4];
    const float* Wh2  = (const float*)d_in[5];
    const float* bh2  = (const float*)d_in[6];
    const float* Wout = (const float*)d_in[7];
    const float* bout = (const float*)d_in[8];
    const float* Wo   = (const float*)d_in[9];
    const float* bo   = (const float*)d_in[10];
    float* out = (float*)d_out;

    const int B = in_sizes[0] / QDIM;   // 65536

    cudaFuncSetAttribute(main_kernel,
                         cudaFuncAttributeMaxDynamicSharedMemorySize, SMEM_BYTES);

    prep_kernel<<<148, 512>>>(Win, Wh1, Wh2, Wout, Wo);
    main_kernel<<<B / 32, 256, SMEM_BYTES>>>(q, bin, bh1, bh2, bout, bo, out);
}

// round 16
// speedup vs baseline: 1.0823x; 1.0421x over previous
#include <cuda_runtime.h>
#include <cuda_bf16.h>
#include <cstdint>

// CholeskyMMNet: mma.sync bf16 hi/lo split; B fragments pre-shuffled in gmem
// (direct LDG); A smem-resident; 32 rows/CTA, 256 thr, 2 CTAs/SM.
// R16: bit-trick truncation split (PRMT+FSUB+cvt.bf16x2), div-free M-fill,
// cross-layer B prefetch chained through bq registers.

#define QDIM 32
#define HDIM 512
#define NTRIL 528
#define BIAS_F 2.0f

// fragment-layout weights: uint4 index ((S*16 + J)*4 + g)*32 + lane
//   g0 = hi, n8 blocks {0,1}; g1 = hi {2,3}; g2 = lo {0,1}; g3 = lo {2,3}
__device__ uint4 g_Fi[2  * 16 * 4 * 32];
__device__ uint4 g_F1[32 * 16 * 4 * 32];
__device__ uint4 g_F2[32 * 16 * 4 * 32];
__device__ uint4 g_Fu[32 * 16 * 4 * 32];
__device__ uint4 g_Fo[32 * 16 * 4 * 32];   // W_o cols 0..511
__device__ uint4 g_Ft[32 * 4 * 32];        // W_o cols 512..527 (padded), (S*4+g)*32+lane

// xs: [32 rows][2048B] = hi 1KB | lo 1KB per row, XOR-swizzled (0..64K)
// Lp overlay: [32][528] fp32 at byte 0 (after final epilogue)
// tail partials: [8 warps][32][16] fp32 at PART_OFF (layer 5 only)
// M staging: dense L bf16, 8 rows, hi|lo, 80B row stride, at LD_BASE
#define XS(r,k,sel) ((r)*2048 + ((((sel)<<10) + ((k)<<1)) ^ (((r)&7)<<4)))
#define PART_OFF 67584
#define LD_BASE  67584
#define LD_SELSZ 20480            // 8 r * 32 rows * 80 B
#define SMEM_BYTES (LD_BASE + 2 * LD_SELSZ)   // 108544

__device__ __forceinline__ uint32_t smem_u32(const void* p) {
    uint32_t a;
    asm("{ .reg .u64 t; cvta.to.shared.u64 t, %1; cvt.u32.u64 %0, t; }" : "=r"(a) : "l"(p));
    return a;
}

#define LDSM4(d, addr) \
    asm volatile("ldmatrix.sync.aligned.m8n8.x4.shared.b16 {%0,%1,%2,%3}, [%4];" \
        : "=r"((d)[0]),"=r"((d)[1]),"=r"((d)[2]),"=r"((d)[3]) : "r"(addr))

// non-volatile: pure register dataflow, ptxas schedules freely (R15 win)
#define MMA16816(c, a, b0, b1) \
    asm("mma.sync.aligned.m16n8k16.row.col.f32.bf16.bf16.f32 " \
        "{%0,%1,%2,%3}, {%4,%5,%6,%7}, {%8,%9}, {%0,%1,%2,%3};" \
        : "+f"((c)[0]),"+f"((c)[1]),"+f"((c)[2]),"+f"((c)[3]) \
        : "r"((a)[0]),"r"((a)[1]),"r"((a)[2]),"r"((a)[3]), "r"(b0),"r"(b1))

// truncation split: hi = top 16 bits (PRMT packs both), lo = exact remainder
// rounded once via cvt.rn.bf16x2. Dropped ll term <= 2^-16 rel (in budget).
__device__ __forceinline__ void split2(float a, float b, uint32_t& h, uint32_t& l) {
    uint32_t ia = __float_as_uint(a), ib = __float_as_uint(b);
    h = __byte_perm(ia, ib, 0x7632);          // [bf16t(b) : bf16t(a)], a in low
    float ra = a - __uint_as_float(ia & 0xFFFF0000u);
    float rb = b - __uint_as_float(ib & 0xFFFF0000u);
    asm("cvt.rn.bf16x2.f32 %0, %1, %2;" : "=r"(l) : "f"(rb), "f"(ra));
}
__device__ __forceinline__ float rd2(const char* sm, int off0, int off1, int idx) {
    __nv_bfloat162 h = *(const __nv_bfloat162*)(sm + off0);
    __nv_bfloat162 l = *(const __nv_bfloat162*)(sm + off1);
    return idx ? (__bfloat162float(h.y) + __bfloat162float(l.y))
               : (__bfloat162float(h.x) + __bfloat162float(l.x));
}

__device__ __forceinline__ void ldB4(uint4* b, const uint4* __restrict__ gF,
                                     int S, int J, int lane) {
    const uint4* p = gF + ((size_t)(S * 16 + J) * 4) * 32 + lane;
    b[0] = __ldg(p);       b[1] = __ldg(p + 32);
    b[2] = __ldg(p + 64);  b[3] = __ldg(p + 96);
}

// 12 MMAs: hh (q0,q1), hl (q2,q3), lh (q0,q1)
__device__ __forceinline__ void mma12(float* A, const uint32_t ah[4], const uint32_t al[4],
                                      const uint4& q0, const uint4& q1,
                                      const uint4& q2, const uint4& q3) {
    MMA16816(A+0,  ah, q0.x, q0.y); MMA16816(A+4,  ah, q0.z, q0.w);
    MMA16816(A+8,  ah, q1.x, q1.y); MMA16816(A+12, ah, q1.z, q1.w);
    MMA16816(A+0,  ah, q2.x, q2.y); MMA16816(A+4,  ah, q2.z, q2.w);
    MMA16816(A+8,  ah, q3.x, q3.y); MMA16816(A+12, ah, q3.z, q3.w);
    MMA16816(A+0,  al, q0.x, q0.y); MMA16816(A+4,  al, q0.z, q0.w);
    MMA16816(A+8,  al, q1.x, q1.y); MMA16816(A+12, al, q1.z, q1.w);
}

// D[32][512] = X @ W^T; warp tile m32 x n64 (J blocks 2w, 2w+1)
// bq: caller-resident B double buffer, preloaded for THIS layer's S=0;
// on the last S, prefetches gFnext's S=0 (hidden under epilogue).
template<int NS, bool RELU, bool RES, bool TO_LP>
__device__ __forceinline__ void tc_layer(char* __restrict__ sm, uint32_t smb,
                                         const uint4* __restrict__ gF,
                                         const uint4* __restrict__ gFnext,
                                         uint4* __restrict__ bq,
                                         const float* __restrict__ bias)
{
    const int tid = threadIdx.x, warp = tid >> 5, lane = tid & 31;
    float acc[64];
    #pragma unroll
    for (int i = 0; i < 64; i++) acc[i] = 0.f;

    #pragma unroll 1
    for (int S = 0; S < NS; S++) {
        const int kk = S * 16 + ((lane >> 4) << 3);
        const int rb = lane & 15;
        uint32_t ah0[4], al0[4], ah1[4], al1[4];
        LDSM4(ah0, smb + XS(rb, kk, 0));
        LDSM4(al0, smb + XS(rb, kk, 1));
        mma12(acc +  0, ah0, al0, bq[0], bq[1], bq[2], bq[3]);
        LDSM4(ah1, smb + XS(16 + rb, kk, 0));
        LDSM4(al1, smb + XS(16 + rb, kk, 1));
        mma12(acc + 32, ah1, al1, bq[0], bq[1], bq[2], bq[3]);
        if (S + 1 < NS) ldB4(bq, gF, S + 1, 2 * warp, lane);
        else            ldB4(bq, gFnext, 0, 2 * warp, lane);   // next-layer prefetch
        mma12(acc + 16, ah0, al0, bq[4], bq[5], bq[6], bq[7]);
        mma12(acc + 48, ah1, al1, bq[4], bq[5], bq[6], bq[7]);
        if (S + 1 < NS) ldB4(bq + 4, gF, S + 1, 2 * warp + 1, lane);
        else            ldB4(bq + 4, gFnext, 0, 2 * warp + 1, lane);
    }
    __syncthreads();   // all mainloop ldsm reads of xs complete

    float tv0 = 0.f, tv1 = 0.f;
    int tr = 0, tcc = 0;
    if (TO_LP) {
        // ---- mini-GEMM: Lp cols 512..527, split-K (warp w -> k chunk 64w..64w+63)
        float at[16];
        #pragma unroll
        for (int i = 0; i < 16; i++) at[i] = 0.f;
        #pragma unroll
        for (int s4 = 0; s4 < 4; s4++) {
            const int S = warp * 4 + s4;
            const int kk = S * 16 + ((lane >> 4) << 3);
            const int rb = lane & 15;
            uint4 th = __ldg(g_Ft + (S * 4 + 0) * 32 + lane);   // hi j0,j1
            uint4 tl = __ldg(g_Ft + (S * 4 + 2) * 32 + lane);   // lo j0,j1
            uint32_t bh0[4], bl0[4], bh1[4], bl1[4];
            LDSM4(bh0, smb + XS(rb, kk, 0));
            LDSM4(bl0, smb + XS(rb, kk, 1));
            LDSM4(bh1, smb + XS(16 + rb, kk, 0));
            LDSM4(bl1, smb + XS(16 + rb, kk, 1));
            MMA16816(at+0,  bh0, th.x, th.y); MMA16816(at+4,  bh0, th.z, th.w);
            MMA16816(at+0,  bh0, tl.x, tl.y); MMA16816(at+4,  bh0, tl.z, tl.w);
            MMA16816(at+0,  bl0, th.x, th.y); MMA16816(at+4,  bl0, th.z, th.w);
            MMA16816(at+8,  bh1, th.x, th.y); MMA16816(at+12, bh1, th.z, th.w);
            MMA16816(at+8,  bh1, tl.x, tl.y); MMA16816(at+12, bh1, tl.z, tl.w);
            MMA16816(at+8,  bl1, th.x, th.y); MMA16816(at+12, bl1, th.z, th.w);
        }
        float* part = (float*)(sm + PART_OFF) + warp * 32 * 16;
        #pragma unroll
        for (int mb = 0; mb < 2; mb++)
            #pragma unroll
            for (int j = 0; j < 2; j++) {
                const int r0 = mb * 16 + (lane >> 2), r1 = r0 + 8;
                const int c  = j * 8 + 2 * (lane & 3);
                const float* a = at + mb * 8 + j * 4;
                part[r0 * 16 + c] = a[0]; part[r0 * 16 + c + 1] = a[1];
                part[r1 * 16 + c] = a[2]; part[r1 * 16 + c + 1] = a[3];
            }
        __syncthreads();   // partials visible; all xs reads complete

        tr = tid >> 3; tcc = (tid & 7) * 2;
        const float* pb = (const float*)(sm + PART_OFF);
        #pragma unroll
        for (int w = 0; w < 8; w++) {
            tv0 += pb[w * 512 + tr * 16 + tcc];
            tv1 += pb[w * 512 + tr * 16 + tcc + 1];
        }
        tv0 += __ldg(bias + 512 + tcc);
        tv1 += __ldg(bias + 513 + tcc);
    }

    #pragma unroll
    for (int mb = 0; mb < 2; mb++)
        #pragma unroll
        for (int Jl = 0; Jl < 2; Jl++)
            #pragma unroll
            for (int j = 0; j < 4; j++) {
                const int c  = warp * 64 + Jl * 32 + j * 8 + 2 * (lane & 3);
                const int r0 = mb * 16 + (lane >> 2), r1 = r0 + 8;
                const float* a = acc + mb * 32 + Jl * 16 + j * 4;
                float b0v = __ldg(bias + c), b1v = __ldg(bias + c + 1);
                float y00 = a[0] + b0v, y01 = a[1] + b1v;
                float y10 = a[2] + b0v, y11 = a[3] + b1v;
                if (RELU) {
                    y00 = fmaxf(y00, 0.f); y01 = fmaxf(y01, 0.f);
                    y10 = fmaxf(y10, 0.f); y11 = fmaxf(y11, 0.f);
                }
                if (RES) {
                    y00 += rd2(sm, XS(r0, c, 0), XS(r0, c, 1), 0);
                    y01 += rd2(sm, XS(r0, c, 0), XS(r0, c, 1), 1);
                    y10 += rd2(sm, XS(r1, c, 0), XS(r1, c, 1), 0);
                    y11 += rd2(sm, XS(r1, c, 0), XS(r1, c, 1), 1);
                }
                if (TO_LP) {
                    float* lp = (float*)sm;
                    lp[r0 * NTRIL + c] = y00; lp[r0 * NTRIL + c + 1] = y01;
                    lp[r1 * NTRIL + c] = y10; lp[r1 * NTRIL + c + 1] = y11;
                } else {
                    uint32_t h, l;
                    split2(y00, y01, h, l);
                    *(uint32_t*)(sm + XS(r0, c, 0)) = h;
                    *(uint32_t*)(sm + XS(r0, c, 1)) = l;
                    split2(y10, y11, h, l);
                    *(uint32_t*)(sm + XS(r1, c, 0)) = h;
                    *(uint32_t*)(sm + XS(r1, c, 1)) = l;
                }
            }
    if (TO_LP) {
        float* lp = (float*)sm;
        lp[tr * NTRIL + 512 + tcc]     = tv0;
        lp[tr * NTRIL + 512 + tcc + 1] = tv1;
    }
    __syncthreads();
}

__global__ void __launch_bounds__(256, 2)
main_kernel(const float* __restrict__ q,
            const float* __restrict__ bin, const float* __restrict__ bh1,
            const float* __restrict__ bh2, const float* __restrict__ bout,
            const float* __restrict__ bo,  float* __restrict__ out)
{
    extern __shared__ char sm[];
    const uint32_t smb = smem_u32(sm);
    const int tid = threadIdx.x, warp = tid >> 5, lane = tid & 31;
    const int row0 = blockIdx.x * 32;

    uint4 bq[8];
    ldB4(bq,     g_Fi, 0, 2 * warp,     lane);   // preload layer-0 S=0
    ldB4(bq + 4, g_Fi, 0, 2 * warp + 1, lane);

    {   // stage q (32x32 fp32) into xs hi/lo
        int r = tid >> 3, kq = (tid & 7) * 4;
        float4 v = *(const float4*)(q + (size_t)(row0 + r) * QDIM + kq);
        uint32_t h, l;
        split2(v.x, v.y, h, l);
        *(uint32_t*)(sm + XS(r, kq, 0)) = h;
        *(uint32_t*)(sm + XS(r, kq, 1)) = l;
        split2(v.z, v.w, h, l);
        *(uint32_t*)(sm + XS(r, kq + 2, 0)) = h;
        *(uint32_t*)(sm + XS(r, kq + 2, 1)) = l;
    }
    __syncthreads();

    tc_layer<2,  true,  false, false>(sm, smb, g_Fi, g_F1, bq, bin);
    tc_layer<32, true,  true,  false>(sm, smb, g_F1, g_F2, bq, bh1);
    tc_layer<32, true,  true,  false>(sm, smb, g_F2, g_Fu, bq, bh2);
    tc_layer<32, false, false, false>(sm, smb, g_Fu, g_Fo, bq, bout);
    tc_layer<32, false, false, true >(sm, smb, g_Fo, g_Fi, bq, bo);  // dummy next

    // ---- M = L @ L^T via MMA, 4 passes x 8 rows ----
    // zero staging ONCE: upper triangle never dirtied; fill overwrites lower+diag
    {
        uint4 z = make_uint4(0, 0, 0, 0);
        uint4* zp = (uint4*)(sm + LD_BASE);
        #pragma unroll
        for (int i = 0; i < (2 * LD_SELSZ) / (16 * 256); i++)
            zp[tid + i * 256] = z;
    }
    __syncthreads();

    const float* lpo = (const float*)sm;   // Lp overlay [32][528]
    for (int pass = 0; pass < 4; pass++) {
        // fill dense L (bf16 hi/lo) for r = pass*8 .. pass*8+7 (div-free)
        for (int e = tid; e < 8 * 512; e += 256) {
            int rr = e >> 9, t = e & 511;
            int i, k; float v;
            if (t < 32) {
                i = t; k = t;
                v = lpo[(pass * 8 + rr) * NTRIL + t] + BIAS_F;
            } else {
                int p2 = t - 32;
                i = (int)((1.0f + sqrtf((float)(1 + 8 * p2))) * 0.5f);
                int base = (i * (i - 1)) >> 1;
                if (p2 < base)          { i--; base = (i * (i - 1)) >> 1; }
                else if (p2 >= base + i){ i++; base = (i * (i - 1)) >> 1; }
                k = p2 - base;
                v = lpo[(pass * 8 + rr) * NTRIL + t];
            }
            __nv_bfloat16 h = __float2bfloat16(v);
            __nv_bfloat16 l = __float2bfloat16(v - __bfloat162float(h));
            int boff = LD_BASE + rr * 2560 + i * 80 + ((k >> 3) << 4) + ((k & 7) << 1);
            *(__nv_bfloat16*)(sm + boff) = h;
            *(__nv_bfloat16*)(sm + boff + LD_SELSZ) = l;
        }
        if (tid < 128) {   // cols 512..527
            int rr = tid >> 4, t = 512 + (tid & 15);
            int p2 = t - 32;
            int i = (int)((1.0f + sqrtf((float)(1 + 8 * p2))) * 0.5f);
            int base = (i * (i - 1)) >> 1;
            if (p2 < base)          { i--; base = (i * (i - 1)) >> 1; }
            else if (p2 >= base + i){ i++; base = (i * (i - 1)) >> 1; }
            int k = p2 - base;
            float v = lpo[(pass * 8 + rr) * NTRIL + t];
            __nv_bfloat16 h = __float2bfloat16(v);
            __nv_bfloat16 l = __float2bfloat16(v - __bfloat162float(h));
            int boff = LD_BASE + rr * 2560 + i * 80 + ((k >> 3) << 4) + ((k & 7) << 1);
            *(__nv_bfloat16*)(sm + boff) = h;
            *(__nv_bfloat16*)(sm + boff + LD_SELSZ) = l;
        }
        __syncthreads();

        // warp w computes M for r = pass*8 + w  (32x32x32 syrk via MMA)
        {
            float am[32];
            #pragma unroll
            for (int i = 0; i < 32; i++) am[i] = 0.f;
            const int rw = lane & 15, half = lane >> 4;
            #pragma unroll
            for (int s = 0; s < 2; s++) {
                uint32_t f0h[4], f0l[4], f1h[4], f1l[4];
                uint32_t a0 = smb + LD_BASE + warp * 2560 + rw * 80 + (2 * s + half) * 16;
                uint32_t a1 = a0 + 16 * 80;
                LDSM4(f0h, a0); LDSM4(f0l, a0 + LD_SELSZ);
                LDSM4(f1h, a1); LDSM4(f1l, a1 + LD_SELSZ);
                // hh
                MMA16816(am+0,  f0h, f0h[0], f0h[2]); MMA16816(am+4,  f0h, f0h[1], f0h[3]);
                MMA16816(am+8,  f0h, f1h[0], f1h[2]); MMA16816(am+12, f0h, f1h[1], f1h[3]);
                MMA16816(am+16, f1h, f0h[0], f0h[2]); MMA16816(am+20, f1h, f0h[1], f0h[3]);
                MMA16816(am+24, f1h, f1h[0], f1h[2]); MMA16816(am+28, f1h, f1h[1], f1h[3]);
                // hl (A hi, B lo)
                MMA16816(am+0,  f0h, f0l[0], f0l[2]); MMA16816(am+4,  f0h, f0l[1], f0l[3]);
                MMA16816(am+8,  f0h, f1l[0], f1l[2]); MMA16816(am+12, f0h, f1l[1], f1l[3]);
                MMA16816(am+16, f1h, f0l[0], f0l[2]); MMA16816(am+20, f1h, f0l[1], f0l[3]);
                MMA16816(am+24, f1h, f1l[0], f1l[2]); MMA16816(am+28, f1h, f1l[1], f1l[3]);
                // lh (A lo, B hi)
                MMA16816(am+0,  f0l, f0h[0], f0h[2]); MMA16816(am+4,  f0l, f0h[1], f0h[3]);
                MMA16816(am+8,  f0l, f1h[0], f1h[2]); MMA16816(am+12, f0l, f1h[1], f1h[3]);
                MMA16816(am+16, f1l, f0h[0], f0h[2]); MMA16816(am+20, f1l, f0h[1], f0h[3]);
                MMA16816(am+24, f1l, f1h[0], f1h[2]); MMA16816(am+28, f1l, f1h[1], f1h[3]);
            }
            float* orow = out + (size_t)(row0 + pass * 8 + warp) * 1024;
            #pragma unroll
            for (int ib = 0; ib < 2; ib++)
                #pragma unroll
                for (int jb = 0; jb < 4; jb++) {
                    const float* a = am + (ib * 4 + jb) * 4;
                    int r0 = ib * 16 + (lane >> 2), r1 = r0 + 8;
                    int col = jb * 8 + 2 * (lane & 3);
                    *(float2*)(orow + r0 * 32 + col) = make_float2(a[0], a[1]);
                    *(float2*)(orow + r1 * 32 + col) = make_float2(a[2], a[3]);
                }
        }
        __syncthreads();   // before next pass's fill overwrites staging
    }
}

// ---------------- prep: weights -> fragment layout (unchanged, RN split) ----------------
#define FI_U32   (2 * 16 * 4 * 32 * 4)
#define FL_U32   (32 * 16 * 4 * 32 * 4)
#define MAIN_U32 (FI_U32 + 4 * FL_U32)
#define FT_U32   (32 * 4 * 32 * 4)

__global__ void prep_kernel(const float* __restrict__ Win, const float* __restrict__ Wh1,
                            const float* __restrict__ Wh2, const float* __restrict__ Wou,
                            const float* __restrict__ Wo)
{
    const int total = MAIN_U32 + FT_U32;
    for (int e = blockIdx.x * blockDim.x + threadIdx.x; e < total;
         e += gridDim.x * blockDim.x) {
        if (e < MAIN_U32) {
            const float* W; uint32_t* dst; int t, ncols;
            if (e < FI_U32) { W = Win; dst = (uint32_t*)g_Fi; t = e; ncols = 512; }
            else {
                int le = e - FI_U32, ly = le / FL_U32;
                t = le - ly * FL_U32;
                ncols = (ly == 3) ? 528 : 512;
                W   = (ly == 0) ? Wh1 : (ly == 1) ? Wh2 : (ly == 2) ? Wou : Wo;
                dst = (uint32_t*)((ly == 0) ? g_F1 : (ly == 1) ? g_F2 :
                                  (ly == 2) ? g_Fu : g_Fo);
            }
            int c = t & 3, l = (t >> 2) & 31, g = (t >> 7) & 3;
            int J = (t >> 9) & 15, S = t >> 13;
            int jl  = (g & 1) * 2 + (c >> 1);
            int sel = g >> 1;
            int n   = J * 32 + jl * 8 + (l >> 2);
            int k0  = S * 16 + (c & 1) * 8 + 2 * (l & 3);
            float v0 = __ldg(W + (size_t)k0 * ncols + n);
            float v1 = __ldg(W + (size_t)(k0 + 1) * ncols + n);
            __nv_bfloat16 h0 = __float2bfloat16(v0), h1 = __float2bfloat16(v1);
            __nv_bfloat16 o0, o1;
            if (sel == 0) { o0 = h0; o1 = h1; }
            else {
                o0 = __float2bfloat16(v0 - __bfloat162float(h0));
                o1 = __float2bfloat16(v1 - __bfloat162float(h1));
            }
            __nv_bfloat162 p = __halves2bfloat162(o0, o1);
            dst[t] = *(uint32_t*)&p;
        } else {
            int t = e - MAIN_U32;
            int c = t & 3, l = (t >> 2) & 31, g = (t >> 7) & 3;
            int S = t >> 9;
            int jl  = (g & 1) * 2 + (c >> 1);
            int sel = g >> 1;
            int n   = 512 + jl * 8 + (l >> 2);
            int k0  = S * 16 + (c & 1) * 8 + 2 * (l & 3);
            float v0 = (n < NTRIL) ? __ldg(Wo + (size_t)k0 * NTRIL + n) : 0.f;
            float v1 = (n < NTRIL) ? __ldg(Wo + (size_t)(k0 + 1) * NTRIL + n) : 0.f;
            __nv_bfloat16 h0 = __float2bfloat16(v0), h1 = __float2bfloat16(v1);
            __nv_bfloat16 o0, o1;
            if (sel == 0) { o0 = h0; o1 = h1; }
            else {
                o0 = __float2bfloat16(v0 - __bfloat162float(h0));
                o1 = __float2bfloat16(v1 - __bfloat162float(h1));
            }
            __nv_bfloat162 p = __halves2bfloat162(o0, o1);
            ((uint32_t*)g_Ft)[t] = *(uint32_t*)&p;
        }
    }
}

extern "C" void kernel_launch(void* const* d_in, const int* in_sizes, int n_in,
                              void* d_out, int out_size)
{
    const float* q    = (const float*)d_in[0];
    const float* Win  = (const float*)d_in[1];
    const float* bin  = (const float*)d_in[2];
    const float* Wh1  = (const float*)d_in[3];
    const float* bh1  = (const float*)d_in[4];
    const float* Wh2  = (const float*)d_in[5];
    const float* bh2  = (const float*)d_in[6];
    const float* Wout = (const float*)d_in[7];
    const float* bout = (const float*)d_in[8];
    const float* Wo   = (const float*)d_in[9];
    const float* bo   = (const float*)d_in[10];
    float* out = (float*)d_out;

    const int B = in_sizes[0] / QDIM;   // 65536

    cudaFuncSetAttribute(main_kernel,
                         cudaFuncAttributeMaxDynamicSharedMemorySize, SMEM_BYTES);

    prep_kernel<<<148, 512>>>(Win, Wh1, Wh2, Wout, Wo);
    main_kernel<<<B / 32, 256, SMEM_BYTES>>>(q, bin, bh1, bh2, bout, bo, out);
}

// round 17
// speedup vs baseline: 1.0945x; 1.0113x over previous
#include <cuda_runtime.h>
#include <cuda_bf16.h>
#include <cstdint>

// CholeskyMMNet: mma.sync bf16 hi/lo split; B fragments pre-shuffled in gmem
// (direct LDG); A smem-resident; 32 rows/CTA, 256 thr, 2 CTAs/SM.
// R17: TO_LP tail runs pre-barrier (one sync removed, overlapped); tril
// (i,k) map precomputed once into a smem uint16 table (kills 4x sqrt loops).

#define QDIM 32
#define HDIM 512
#define NTRIL 528
#define BIAS_F 2.0f

// fragment-layout weights: uint4 index ((S*16 + J)*4 + g)*32 + lane
//   g0 = hi, n8 blocks {0,1}; g1 = hi {2,3}; g2 = lo {0,1}; g3 = lo {2,3}
__device__ uint4 g_Fi[2  * 16 * 4 * 32];
__device__ uint4 g_F1[32 * 16 * 4 * 32];
__device__ uint4 g_F2[32 * 16 * 4 * 32];
__device__ uint4 g_Fu[32 * 16 * 4 * 32];
__device__ uint4 g_Fo[32 * 16 * 4 * 32];   // W_o cols 0..511
__device__ uint4 g_Ft[32 * 4 * 32];        // W_o cols 512..527 (padded), (S*4+g)*32+lane

// xs: [32 rows][2048B] = hi 1KB | lo 1KB per row, XOR-swizzled (0..64K)
// Lp overlay: [32][528] fp32 at byte 0 (after final epilogue)
// tail partials: [8 warps][32][16] fp32 at PART_OFF (layer 5 only)
// M staging: dense L bf16, 8 rows, hi|lo, 80B row stride, at LD_BASE
// tril table: 528 uint16 at TAB_OFF
#define XS(r,k,sel) ((r)*2048 + ((((sel)<<10) + ((k)<<1)) ^ (((r)&7)<<4)))
#define PART_OFF 67584
#define LD_BASE  67584
#define LD_SELSZ 20480            // 8 r * 32 rows * 80 B
#define TAB_OFF  108544
#define SMEM_BYTES 109632

__device__ __forceinline__ uint32_t smem_u32(const void* p) {
    uint32_t a;
    asm("{ .reg .u64 t; cvta.to.shared.u64 t, %1; cvt.u32.u64 %0, t; }" : "=r"(a) : "l"(p));
    return a;
}

#define LDSM4(d, addr) \
    asm volatile("ldmatrix.sync.aligned.m8n8.x4.shared.b16 {%0,%1,%2,%3}, [%4];" \
        : "=r"((d)[0]),"=r"((d)[1]),"=r"((d)[2]),"=r"((d)[3]) : "r"(addr))

// non-volatile: pure register dataflow, ptxas schedules freely (R15 win)
#define MMA16816(c, a, b0, b1) \
    asm("mma.sync.aligned.m16n8k16.row.col.f32.bf16.bf16.f32 " \
        "{%0,%1,%2,%3}, {%4,%5,%6,%7}, {%8,%9}, {%0,%1,%2,%3};" \
        : "+f"((c)[0]),"+f"((c)[1]),"+f"((c)[2]),"+f"((c)[3]) \
        : "r"((a)[0]),"r"((a)[1]),"r"((a)[2]),"r"((a)[3]), "r"(b0),"r"(b1))

// truncation split: hi = top 16 bits (PRMT packs both), lo = exact remainder
// rounded once via cvt.rn.bf16x2. Dropped ll term <= 2^-16 rel (in budget).
__device__ __forceinline__ void split2(float a, float b, uint32_t& h, uint32_t& l) {
    uint32_t ia = __float_as_uint(a), ib = __float_as_uint(b);
    h = __byte_perm(ia, ib, 0x7632);          // [bf16t(b) : bf16t(a)]
    float ra = a - __uint_as_float(ia & 0xFFFF0000u);
    float rb = b - __uint_as_float(ib & 0xFFFF0000u);
    asm("cvt.rn.bf16x2.f32 %0, %1, %2;" : "=r"(l) : "f"(rb), "f"(ra));
}
__device__ __forceinline__ float rd2(const char* sm, int off0, int off1, int idx) {
    __nv_bfloat162 h = *(const __nv_bfloat162*)(sm + off0);
    __nv_bfloat162 l = *(const __nv_bfloat162*)(sm + off1);
    return idx ? (__bfloat162float(h.y) + __bfloat162float(l.y))
               : (__bfloat162float(h.x) + __bfloat162float(l.x));
}

__device__ __forceinline__ void ldB4(uint4* b, const uint4* __restrict__ gF,
                                     int S, int J, int lane) {
    const uint4* p = gF + ((size_t)(S * 16 + J) * 4) * 32 + lane;
    b[0] = __ldg(p);       b[1] = __ldg(p + 32);
    b[2] = __ldg(p + 64);  b[3] = __ldg(p + 96);
}

// 12 MMAs: hh (q0,q1), hl (q2,q3), lh (q0,q1)
__device__ __forceinline__ void mma12(float* A, const uint32_t ah[4], const uint32_t al[4],
                                      const uint4& q0, const uint4& q1,
                                      const uint4& q2, const uint4& q3) {
    MMA16816(A+0,  ah, q0.x, q0.y); MMA16816(A+4,  ah, q0.z, q0.w);
    MMA16816(A+8,  ah, q1.x, q1.y); MMA16816(A+12, ah, q1.z, q1.w);
    MMA16816(A+0,  ah, q2.x, q2.y); MMA16816(A+4,  ah, q2.z, q2.w);
    MMA16816(A+8,  ah, q3.x, q3.y); MMA16816(A+12, ah, q3.z, q3.w);
    MMA16816(A+0,  al, q0.x, q0.y); MMA16816(A+4,  al, q0.z, q0.w);
    MMA16816(A+8,  al, q1.x, q1.y); MMA16816(A+12, al, q1.z, q1.w);
}

// D[32][512] = X @ W^T; warp tile m32 x n64 (J blocks 2w, 2w+1)
// bq: caller-resident B double buffer, preloaded for THIS layer's S=0;
// on the last S, prefetches gFnext's S=0 (hidden under epilogue).
template<int NS, bool RELU, bool RES, bool TO_LP>
__device__ __forceinline__ void tc_layer(char* __restrict__ sm, uint32_t smb,
                                         const uint4* __restrict__ gF,
                                         const uint4* __restrict__ gFnext,
                                         uint4* __restrict__ bq,
                                         const float* __restrict__ bias)
{
    const int tid = threadIdx.x, warp = tid >> 5, lane = tid & 31;
    float acc[64];
    #pragma unroll
    for (int i = 0; i < 64; i++) acc[i] = 0.f;

    #pragma unroll 1
    for (int S = 0; S < NS; S++) {
        const int kk = S * 16 + ((lane >> 4) << 3);
        const int rb = lane & 15;
        uint32_t ah0[4], al0[4], ah1[4], al1[4];
        LDSM4(ah0, smb + XS(rb, kk, 0));
        LDSM4(al0, smb + XS(rb, kk, 1));
        mma12(acc +  0, ah0, al0, bq[0], bq[1], bq[2], bq[3]);
        LDSM4(ah1, smb + XS(16 + rb, kk, 0));
        LDSM4(al1, smb + XS(16 + rb, kk, 1));
        mma12(acc + 32, ah1, al1, bq[0], bq[1], bq[2], bq[3]);
        if (S + 1 < NS) ldB4(bq, gF, S + 1, 2 * warp, lane);
        else            ldB4(bq, gFnext, 0, 2 * warp, lane);   // next-layer prefetch
        mma12(acc + 16, ah0, al0, bq[4], bq[5], bq[6], bq[7]);
        mma12(acc + 48, ah1, al1, bq[4], bq[5], bq[6], bq[7]);
        if (S + 1 < NS) ldB4(bq + 4, gF, S + 1, 2 * warp + 1, lane);
        else            ldB4(bq + 4, gFnext, 0, 2 * warp + 1, lane);
    }

    float tv0 = 0.f, tv1 = 0.f;
    int tr = 0, tcc = 0;
    if (TO_LP) {
        // ---- tail mini-GEMM BEFORE the barrier: only READS xs, writes its own
        // part region. Overlaps with other warps still in their mainloop.
        float at[16];
        #pragma unroll
        for (int i = 0; i < 16; i++) at[i] = 0.f;
        #pragma unroll
        for (int s4 = 0; s4 < 4; s4++) {
            const int S = warp * 4 + s4;
            const int kk = S * 16 + ((lane >> 4) << 3);
            const int rb = lane & 15;
            uint4 th = __ldg(g_Ft + (S * 4 + 0) * 32 + lane);   // hi j0,j1
            uint4 tl = __ldg(g_Ft + (S * 4 + 2) * 32 + lane);   // lo j0,j1
            uint32_t bh0[4], bl0[4], bh1[4], bl1[4];
            LDSM4(bh0, smb + XS(rb, kk, 0));
            LDSM4(bl0, smb + XS(rb, kk, 1));
            LDSM4(bh1, smb + XS(16 + rb, kk, 0));
            LDSM4(bl1, smb + XS(16 + rb, kk, 1));
            MMA16816(at+0,  bh0, th.x, th.y); MMA16816(at+4,  bh0, th.z, th.w);
            MMA16816(at+0,  bh0, tl.x, tl.y); MMA16816(at+4,  bh0, tl.z, tl.w);
            MMA16816(at+0,  bl0, th.x, th.y); MMA16816(at+4,  bl0, th.z, th.w);
            MMA16816(at+8,  bh1, th.x, th.y); MMA16816(at+12, bh1, th.z, th.w);
            MMA16816(at+8,  bh1, tl.x, tl.y); MMA16816(at+12, bh1, tl.z, tl.w);
            MMA16816(at+8,  bl1, th.x, th.y); MMA16816(at+12, bl1, th.z, th.w);
        }
        float* part = (float*)(sm + PART_OFF) + warp * 32 * 16;
        #pragma unroll
        for (int mb = 0; mb < 2; mb++)
            #pragma unroll
            for (int j = 0; j < 2; j++) {
                const int r0 = mb * 16 + (lane >> 2), r1 = r0 + 8;
                const int c  = j * 8 + 2 * (lane & 3);
                const float* a = at + mb * 8 + j * 4;
                part[r0 * 16 + c] = a[0]; part[r0 * 16 + c + 1] = a[1];
                part[r1 * 16 + c] = a[2]; part[r1 * 16 + c + 1] = a[3];
            }
    }
    __syncthreads();   // ALL xs reads (mainloop + tail) done; partials visible

    if (TO_LP) {
        tr = tid >> 3; tcc = (tid & 7) * 2;
        const float* pb = (const float*)(sm + PART_OFF);
        #pragma unroll
        for (int w = 0; w < 8; w++) {
            tv0 += pb[w * 512 + tr * 16 + tcc];
            tv1 += pb[w * 512 + tr * 16 + tcc + 1];
        }
        tv0 += __ldg(bias + 512 + tcc);
        tv1 += __ldg(bias + 513 + tcc);
    }

    #pragma unroll
    for (int mb = 0; mb < 2; mb++)
        #pragma unroll
        for (int Jl = 0; Jl < 2; Jl++)
            #pragma unroll
            for (int j = 0; j < 4; j++) {
                const int c  = warp * 64 + Jl * 32 + j * 8 + 2 * (lane & 3);
                const int r0 = mb * 16 + (lane >> 2), r1 = r0 + 8;
                const float* a = acc + mb * 32 + Jl * 16 + j * 4;
                float b0v = __ldg(bias + c), b1v = __ldg(bias + c + 1);
                float y00 = a[0] + b0v, y01 = a[1] + b1v;
                float y10 = a[2] + b0v, y11 = a[3] + b1v;
                if (RELU) {
                    y00 = fmaxf(y00, 0.f); y01 = fmaxf(y01, 0.f);
                    y10 = fmaxf(y10, 0.f); y11 = fmaxf(y11, 0.f);
                }
                if (RES) {
                    y00 += rd2(sm, XS(r0, c, 0), XS(r0, c, 1), 0);
                    y01 += rd2(sm, XS(r0, c, 0), XS(r0, c, 1), 1);
                    y10 += rd2(sm, XS(r1, c, 0), XS(r1, c, 1), 0);
                    y11 += rd2(sm, XS(r1, c, 0), XS(r1, c, 1), 1);
                }
                if (TO_LP) {
                    float* lp = (float*)sm;
                    lp[r0 * NTRIL + c] = y00; lp[r0 * NTRIL + c + 1] = y01;
                    lp[r1 * NTRIL + c] = y10; lp[r1 * NTRIL + c + 1] = y11;
                } else {
                    uint32_t h, l;
                    split2(y00, y01, h, l);
                    *(uint32_t*)(sm + XS(r0, c, 0)) = h;
                    *(uint32_t*)(sm + XS(r0, c, 1)) = l;
                    split2(y10, y11, h, l);
                    *(uint32_t*)(sm + XS(r1, c, 0)) = h;
                    *(uint32_t*)(sm + XS(r1, c, 1)) = l;
                }
            }
    if (TO_LP) {
        float* lp = (float*)sm;
        lp[tr * NTRIL + 512 + tcc]     = tv0;
        lp[tr * NTRIL + 512 + tcc + 1] = tv1;
    }
    __syncthreads();
}

__global__ void __launch_bounds__(256, 2)
main_kernel(const float* __restrict__ q,
            const float* __restrict__ bin, const float* __restrict__ bh1,
            const float* __restrict__ bh2, const float* __restrict__ bout,
            const float* __restrict__ bo,  float* __restrict__ out)
{
    extern __shared__ char sm[];
    const uint32_t smb = smem_u32(sm);
    const int tid = threadIdx.x, warp = tid >> 5, lane = tid & 31;
    const int row0 = blockIdx.x * 32;

    uint4 bq[8];
    ldB4(bq,     g_Fi, 0, 2 * warp,     lane);   // preload layer-0 S=0
    ldB4(bq + 4, g_Fi, 0, 2 * warp + 1, lane);

    {   // stage q (32x32 fp32) into xs hi/lo
        int r = tid >> 3, kq = (tid & 7) * 4;
        float4 v = *(const float4*)(q + (size_t)(row0 + r) * QDIM + kq);
        uint32_t h, l;
        split2(v.x, v.y, h, l);
        *(uint32_t*)(sm + XS(r, kq, 0)) = h;
        *(uint32_t*)(sm + XS(r, kq, 1)) = l;
        split2(v.z, v.w, h, l);
        *(uint32_t*)(sm + XS(r, kq + 2, 0)) = h;
        *(uint32_t*)(sm + XS(r, kq + 2, 1)) = l;
    }
    // tril index table: t -> (i<<8)|k, computed once (sqrt path)
    for (int t = tid; t < NTRIL; t += 256) {
        int i, k;
        if (t < 32) { i = t; k = t; }
        else {
            int p2 = t - 32;
            i = (int)((1.0f + sqrtf((float)(1 + 8 * p2))) * 0.5f);
            int base = (i * (i - 1)) >> 1;
            if (p2 < base)           { i--; base = (i * (i - 1)) >> 1; }
            else if (p2 >= base + i) { i++; base = (i * (i - 1)) >> 1; }
            k = p2 - base;
        }
        *(uint16_t*)(sm + TAB_OFF + t * 2) = (uint16_t)((i << 8) | k);
    }
    __syncthreads();

    tc_layer<2,  true,  false, false>(sm, smb, g_Fi, g_F1, bq, bin);
    tc_layer<32, true,  true,  false>(sm, smb, g_F1, g_F2, bq, bh1);
    tc_layer<32, true,  true,  false>(sm, smb, g_F2, g_Fu, bq, bh2);
    tc_layer<32, false, false, false>(sm, smb, g_Fu, g_Fo, bq, bout);
    tc_layer<32, false, false, true >(sm, smb, g_Fo, g_Fi, bq, bo);  // dummy next

    // ---- M = L @ L^T via MMA, 4 passes x 8 rows ----
    // zero staging ONCE: upper triangle never dirtied; fill overwrites lower+diag
    {
        uint4 z = make_uint4(0, 0, 0, 0);
        uint4* zp = (uint4*)(sm + LD_BASE);
        #pragma unroll
        for (int i = 0; i < (2 * LD_SELSZ) / (16 * 256); i++)
            zp[tid + i * 256] = z;
    }
    __syncthreads();

    const float* lpo = (const float*)sm;   // Lp overlay [32][528]
    for (int pass = 0; pass < 4; pass++) {
        // fill dense L (bf16 hi/lo) for r = pass*8 .. pass*8+7 via table
        for (int e = tid; e < 8 * NTRIL; e += 256) {
            int rr = e / NTRIL, t = e - rr * NTRIL;
            uint32_t ik = *(const uint16_t*)(sm + TAB_OFF + t * 2);
            int i = ik >> 8, k = ik & 255;
            float v = lpo[(pass * 8 + rr) * NTRIL + t];
            if (t < 32) v += BIAS_F;
            __nv_bfloat16 h = __float2bfloat16(v);
            __nv_bfloat16 l = __float2bfloat16(v - __bfloat162float(h));
            int boff = LD_BASE + rr * 2560 + i * 80 + ((k >> 3) << 4) + ((k & 7) << 1);
            *(__nv_bfloat16*)(sm + boff) = h;
            *(__nv_bfloat16*)(sm + boff + LD_SELSZ) = l;
        }
        __syncthreads();

        // warp w computes M for r = pass*8 + w  (32x32x32 syrk via MMA)
        {
            float am[32];
            #pragma unroll
            for (int i = 0; i < 32; i++) am[i] = 0.f;
            const int rw = lane & 15, half = lane >> 4;
            #pragma unroll
            for (int s = 0; s < 2; s++) {
                uint32_t f0h[4], f0l[4], f1h[4], f1l[4];
                uint32_t a0 = smb + LD_BASE + warp * 2560 + rw * 80 + (2 * s + half) * 16;
                uint32_t a1 = a0 + 16 * 80;
                LDSM4(f0h, a0); LDSM4(f0l, a0 + LD_SELSZ);
                LDSM4(f1h, a1); LDSM4(f1l, a1 + LD_SELSZ);
                // hh
                MMA16816(am+0,  f0h, f0h[0], f0h[2]); MMA16816(am+4,  f0h, f0h[1], f0h[3]);
                MMA16816(am+8,  f0h, f1h[0], f1h[2]); MMA16816(am+12, f0h, f1h[1], f1h[3]);
                MMA16816(am+16, f1h, f0h[0], f0h[2]); MMA16816(am+20, f1h, f0h[1], f0h[3]);
                MMA16816(am+24, f1h, f1h[0], f1h[2]); MMA16816(am+28, f1h, f1h[1], f1h[3]);
                // hl (A hi, B lo)
                MMA16816(am+0,  f0h, f0l[0], f0l[2]); MMA16816(am+4,  f0h, f0l[1], f0l[3]);
                MMA16816(am+8,  f0h, f1l[0], f1l[2]); MMA16816(am+12, f0h, f1l[1], f1l[3]);
                MMA16816(am+16, f1h, f0l[0], f0l[2]); MMA16816(am+20, f1h, f0l[1], f0l[3]);
                MMA16816(am+24, f1h, f1l[0], f1l[2]); MMA16816(am+28, f1h, f1l[1], f1l[3]);
                // lh (A lo, B hi)
                MMA16816(am+0,  f0l, f0h[0], f0h[2]); MMA16816(am+4,  f0l, f0h[1], f0h[3]);
                MMA16816(am+8,  f0l, f1h[0], f1h[2]); MMA16816(am+12, f0l, f1h[1], f1h[3]);
                MMA16816(am+16, f1l, f0h[0], f0h[2]); MMA16816(am+20, f1l, f0h[1], f0h[3]);
                MMA16816(am+24, f1l, f1h[0], f1h[2]); MMA16816(am+28, f1l, f1h[1], f1h[3]);
            }
            float* orow = out + (size_t)(row0 + pass * 8 + warp) * 1024;
            #pragma unroll
            for (int ib = 0; ib < 2; ib++)
                #pragma unroll
                for (int jb = 0; jb < 4; jb++) {
                    const float* a = am + (ib * 4 + jb) * 4;
                    int r0 = ib * 16 + (lane >> 2), r1 = r0 + 8;
                    int col = jb * 8 + 2 * (lane & 3);
                    *(float2*)(orow + r0 * 32 + col) = make_float2(a[0], a[1]);
                    *(float2*)(orow + r1 * 32 + col) = make_float2(a[2], a[3]);
                }
        }
        __syncthreads();   // before next pass's fill overwrites staging
    }
}

// ---------------- prep: weights -> fragment layout (unchanged, RN split) ----------------
#define FI_U32   (2 * 16 * 4 * 32 * 4)
#define FL_U32   (32 * 16 * 4 * 32 * 4)
#define MAIN_U32 (FI_U32 + 4 * FL_U32)
#define FT_U32   (32 * 4 * 32 * 4)

__global__ void prep_kernel(const float* __restrict__ Win, const float* __restrict__ Wh1,
                            const float* __restrict__ Wh2, const float* __restrict__ Wou,
                            const float* __restrict__ Wo)
{
    const int total = MAIN_U32 + FT_U32;
    for (int e = blockIdx.x * blockDim.x + threadIdx.x; e < total;
         e += gridDim.x * blockDim.x) {
        if (e < MAIN_U32) {
            const float* W; uint32_t* dst; int t, ncols;
            if (e < FI_U32) { W = Win; dst = (uint32_t*)g_Fi; t = e; ncols = 512; }
            else {
                int le = e - FI_U32, ly = le / FL_U32;
                t = le - ly * FL_U32;
                ncols = (ly == 3) ? 528 : 512;
                W   = (ly == 0) ? Wh1 : (ly == 1) ? Wh2 : (ly == 2) ? Wou : Wo;
                dst = (uint32_t*)((ly == 0) ? g_F1 : (ly == 1) ? g_F2 :
                                  (ly == 2) ? g_Fu : g_Fo);
            }
            int c = t & 3, l = (t >> 2) & 31, g = (t >> 7) & 3;
            int J = (t >> 9) & 15, S = t >> 13;
            int jl  = (g & 1) * 2 + (c >> 1);
            int sel = g >> 1;
            int n   = J * 32 + jl * 8 + (l >> 2);
            int k0  = S * 16 + (c & 1) * 8 + 2 * (l & 3);
            float v0 = __ldg(W + (size_t)k0 * ncols + n);
            float v1 = __ldg(W + (size_t)(k0 + 1) * ncols + n);
            __nv_bfloat16 h0 = __float2bfloat16(v0), h1 = __float2bfloat16(v1);
            __nv_bfloat16 o0, o1;
            if (sel == 0) { o0 = h0; o1 = h1; }
            else {
                o0 = __float2bfloat16(v0 - __bfloat162float(h0));
                o1 = __float2bfloat16(v1 - __bfloat162float(h1));
            }
            __nv_bfloat162 p = __halves2bfloat162(o0, o1);
            dst[t] = *(uint32_t*)&p;
        } else {
            int t = e - MAIN_U32;
            int c = t & 3, l = (t >> 2) & 31, g = (t >> 7) & 3;
            int S = t >> 9;
            int jl  = (g & 1) * 2 + (c >> 1);
            int sel = g >> 1;
            int n   = 512 + jl * 8 + (l >> 2);
            int k0  = S * 16 + (c & 1) * 8 + 2 * (l & 3);
            float v0 = (n < NTRIL) ? __ldg(Wo + (size_t)k0 * NTRIL + n) : 0.f;
            float v1 = (n < NTRIL) ? __ldg(Wo + (size_t)(k0 + 1) * NTRIL + n) : 0.f;
            __nv_bfloat16 h0 = __float2bfloat16(v0), h1 = __float2bfloat16(v1);
            __nv_bfloat16 o0, o1;
            if (sel == 0) { o0 = h0; o1 = h1; }
            else {
                o0 = __float2bfloat16(v0 - __bfloat162float(h0));
                o1 = __float2bfloat16(v1 - __bfloat162float(h1));
            }
            __nv_bfloat162 p = __halves2bfloat162(o0, o1);
            ((uint32_t*)g_Ft)[t] = *(uint32_t*)&p;
        }
    }
}

extern "C" void kernel_launch(void* const* d_in, const int* in_sizes, int n_in,
                              void* d_out, int out_size)
{
    const float* q    = (const float*)d_in[0];
    const float* Win  = (const float*)d_in[1];
    const float* bin  = (const float*)d_in[2];
    const float* Wh1  = (const float*)d_in[3];
    const float* bh1  = (const float*)d_in[4];
    const float* Wh2  = (const float*)d_in[5];
    const float* bh2  = (const float*)d_in[6];
    const float* Wout = (const float*)d_in[7];
    const float* bout = (const float*)d_in[8];
    const float* Wo   = (const float*)d_in[9];
    const float* bo   = (const float*)d_in[10];
    float* out = (float*)d_out;

    const int B = in_sizes[0] / QDIM;   // 65536

    cudaFuncSetAttribute(main_kernel,
                         cudaFuncAttributeMaxDynamicSharedMemorySize, SMEM_BYTES);

    prep_kernel<<<148, 512>>>(Win, Wh1, Wh2, Wout, Wo);
    main_kernel<<<B / 32, 256, SMEM_BYTES>>>(q, bin, bh1, bh2, bout, bo, out);
}